// round 1
// baseline (speedup 1.0000x reference)
#include <cuda_runtime.h>

// Closed-form constants (double-precision derived, truncated to fp32).
#define Y00f  0.28209479177387814f   // 1/(2*sqrt(pi))
#define N10f  0.48860251190291992f   // sqrt(3/(4pi))
#define N20f  0.63078313050504001f   // sqrt(5/(4pi))
#define C21f  (-1.09254843059207907f) // -(1/2)*sqrt(15/pi)  (l=2,|m|=1 combined)
#define C22f  0.54627421529603953f   // (1/4)*sqrt(15/pi)   (l=2,|m|=2 combined)
#define K20f  0.35355339059327379f   // 1/(2*sqrt(2))
#define K21f  0.20412414523193152f   // 1/(2*sqrt(6))
#define K30f  0.06415002990995843f   // 1/(9*sqrt(3))        (mult (rho^2-6rho+6))
#define K31f  0.04536092116208279f   // sqrt(1/486)
#define K32f  0.02028602047074832f   // sqrt(8/19440)

struct Coeffs { float c[14]; };

__device__ __forceinline__ float eval_point(float r, float theta, float phi,
                                            const Coeffs& C) {
    float st, ct;
    __sincosf(theta, &st, &ct);
    float sp, cp;
    __sincosf(phi, &sp, &cp);
    float c2p = cp * cp - sp * sp;   // cos(2*phi)
    float s2p = 2.0f * sp * cp;      // sin(2*phi)

    // e^{-r/6}; powers give e^{-r/3}, e^{-r/2}, e^{-r}
    float t  = __expf(r * (-1.0f / 6.0f));
    float t2 = t * t;      // e^{-r/3}
    float t3 = t2 * t;     // e^{-r/2}
    float t6 = t3 * t3;    // e^{-r}

    float rho = r * (2.0f / 3.0f);

    // Radial parts
    float R10 = 2.0f * t6;
    float R20 = K20f * (2.0f - r) * t3;
    float R21 = K21f * r * t3;
    float R30 = K30f * ((rho - 6.0f) * rho + 6.0f) * t2;
    float R31 = K31f * (4.0f - rho) * rho * t2;
    float R32 = K32f * rho * rho * t2;

    // l = 0 block (Y00 * sum)
    float out = Y00f * (C.c[0] * R10 + C.c[1] * R20 + C.c[5] * R30);

    // l = 1 block: m=0 -> N10*ct ; m=+1 -> -N10*st*cos(phi) ; m=-1 -> -N10*st*sin(phi)
    float l1m0 = C.c[3] * R21 + C.c[7] * R31;
    float l1c  = C.c[4] * R21 + C.c[8] * R31;
    float l1s  = C.c[2] * R21 + C.c[6] * R31;
    out += N10f * (ct * l1m0 - st * (l1c * cp + l1s * sp));

    // l = 2 block (only n=3)
    float ang2 = C.c[11] * (N20f * (1.5f * ct * ct - 0.5f))
               + C21f * ct * st * (C.c[12] * cp + C.c[10] * sp)
               + C22f * st * st * (C.c[13] * c2p + C.c[9] * s2p);
    out += R32 * ang2;

    return out;
}

__global__ __launch_bounds__(256)
void orbital_eval_kernel(const float* __restrict__ pos,
                         const float* __restrict__ coeffs,
                         float* __restrict__ out,
                         int n4, int n) {
    int i = blockIdx.x * blockDim.x + threadIdx.x;

    Coeffs C;
#pragma unroll
    for (int k = 0; k < 14; k++) C.c[k] = __ldg(&coeffs[k]);

    if (i < n4) {
        const float4* p4 = reinterpret_cast<const float4*>(pos);
        float4 a = p4[3 * i + 0];
        float4 b = p4[3 * i + 1];
        float4 d = p4[3 * i + 2];
        // 4 points packed: (a.x,a.y,a.z) (a.w,b.x,b.y) (b.z,b.w,d.x) (d.y,d.z,d.w)
        float4 o;
        o.x = eval_point(a.x, a.y, a.z, C);
        o.y = eval_point(a.w, b.x, b.y, C);
        o.z = eval_point(b.z, b.w, d.x, C);
        o.w = eval_point(d.y, d.z, d.w, C);
        reinterpret_cast<float4*>(out)[i] = o;
    }

    // Scalar tail (n % 4 != 0); first few threads of the grid handle it.
    int tail = n - n4 * 4;
    if (i < tail) {
        int idx = n4 * 4 + i;
        out[idx] = eval_point(pos[3 * idx], pos[3 * idx + 1], pos[3 * idx + 2], C);
    }
}

extern "C" void kernel_launch(void* const* d_in, const int* in_sizes, int n_in,
                              void* d_out, int out_size) {
    const float* pos    = (const float*)d_in[0];   // (2048, 4096, 3) fp32
    const float* coeffs = (const float*)d_in[1];   // (14,) fp32
    float* out          = (float*)d_out;           // (2048, 4096) fp32

    int n  = out_size;        // number of points
    int n4 = n / 4;           // float4 groups

    int threads = 256;
    int groups  = (n4 > 0) ? n4 : 1;
    int blocks  = (groups + threads - 1) / threads;
    orbital_eval_kernel<<<blocks, threads>>>(pos, coeffs, out, n4, n);
}

// round 2
// speedup vs baseline: 1.0023x; 1.0023x over previous
#include <cuda_runtime.h>

// Closed-form normalization constants.
#define Y00f  0.28209479177387814f    // 1/(2*sqrt(pi))
#define N10f  0.48860251190291992f    // sqrt(3/(4pi))
#define N20f  0.63078313050504001f    // sqrt(5/(4pi))
#define C21f  (-1.09254843059207907f) // -(1/2)*sqrt(15/pi)
#define C22f  0.54627421529603953f    // (1/4)*sqrt(15/pi)
#define K20f  0.35355339059327379f    // 1/(2*sqrt(2))
#define K21f  0.20412414523193152f    // 1/(2*sqrt(6))
#define K30f  0.06415002990995843f    // 1/(9*sqrt(3))
#define K31f  0.04536092116208279f    // sqrt(1/486)
#define K32f  0.02028602047074832f    // sqrt(8/19440)

typedef unsigned long long u64;

__device__ __forceinline__ u64 pk(float lo, float hi) {
    u64 r; asm("mov.b64 %0,{%1,%2};" : "=l"(r) : "f"(lo), "f"(hi)); return r;
}
__device__ __forceinline__ void upk(u64 v, float& lo, float& hi) {
    asm("mov.b64 {%0,%1},%2;" : "=f"(lo), "=f"(hi) : "l"(v));
}
__device__ __forceinline__ u64 f2mul(u64 a, u64 b) {
    u64 d; asm("mul.rn.f32x2 %0,%1,%2;" : "=l"(d) : "l"(a), "l"(b)); return d;
}
__device__ __forceinline__ u64 f2fma(u64 a, u64 b, u64 c) {
    u64 d; asm("fma.rn.f32x2 %0,%1,%2,%3;" : "=l"(d) : "l"(a), "l"(b), "l"(c)); return d;
}
__device__ __forceinline__ u64 f2add(u64 a, u64 b) {
    u64 d; asm("add.rn.f32x2 %0,%1,%2;" : "=l"(d) : "l"(a), "l"(b)); return d;
}

struct A14 { u64 a[14]; };

// Per-point scalar prep: MUFU ops + constant-immediate ops only.
struct Prep { float r, t, ct, st, cp, sp, rho, tmr, fmr, l30, nspsq, ct2t; };

__device__ __forceinline__ Prep prep(float r, float th, float ph) {
    Prep p;
    p.r = r;
    __sincosf(th, &p.st, &p.ct);
    __sincosf(ph, &p.sp, &p.cp);
    p.t     = __expf(r * (-1.0f / 6.0f));     // e^{-r/6}
    p.rho   = r * (2.0f / 3.0f);
    p.tmr   = 2.0f - r;
    p.fmr   = 4.0f - p.rho;
    p.l30   = fmaf(p.rho - 6.0f, p.rho, 6.0f); // rho^2 - 6 rho + 6
    p.nspsq = p.sp * (-p.sp);                  // -sin^2(phi)
    p.ct2t  = fmaf(p.ct * p.ct, 1.5f, -0.5f);  // (3cos^2-1)/2
    return p;
}

// Packed evaluation of two points.
__device__ __forceinline__ u64 eval_pair(const Prep& p0, const Prep& p1, const A14& A) {
    u64 R   = pk(p0.r,   p1.r),   T    = pk(p0.t,    p1.t);
    u64 CT  = pk(p0.ct,  p1.ct),  ST   = pk(p0.st,   p1.st);
    u64 CP  = pk(p0.cp,  p1.cp),  SP   = pk(p0.sp,   p1.sp);
    u64 RHO = pk(p0.rho, p1.rho), TMR  = pk(p0.tmr,  p1.tmr);
    u64 FMR = pk(p0.fmr, p1.fmr), L30  = pk(p0.l30,  p1.l30);
    u64 NSQ = pk(p0.nspsq, p1.nspsq), CT2T = pk(p0.ct2t, p1.ct2t);

    u64 T2 = f2mul(T, T), T3 = f2mul(T2, T), T6 = f2mul(T3, T3);
    u64 G3 = f2mul(FMR, RHO);           // (4-rho)*rho
    u64 Q  = f2mul(RHO, RHO);           // rho^2
    u64 C2P  = f2fma(CP, CP, NSQ);      // cos(2phi)
    u64 SPCP = f2mul(SP, CP);
    u64 S2P  = f2add(SPCP, SPCP);       // sin(2phi)
    u64 CTST = f2mul(CT, ST), ST2 = f2mul(ST, ST);

    // n=2, l=1 + n=2, l=0 block (×t3)
    u64 X1 = f2fma(CP, A.a[3], f2mul(SP, A.a[4]));
    X1     = f2fma(CT, A.a[2], f2mul(ST, X1));
    u64 B3 = f2fma(TMR, A.a[1], f2mul(R, X1));

    // n=3, l=0..1 block (×t2)
    u64 X2 = f2fma(CP, A.a[7], f2mul(SP, A.a[8]));
    X2     = f2fma(CT, A.a[6], f2mul(ST, X2));
    u64 P2 = f2fma(L30, A.a[5], f2mul(G3, X2));

    // n=3, l=2 block
    u64 Y = f2fma(CP, A.a[10], f2mul(SP, A.a[11]));
    Y     = f2mul(CTST, Y);
    u64 Z = f2fma(C2P, A.a[12], f2mul(S2P, A.a[13]));
    u64 W = f2fma(ST2, Z, f2fma(CT2T, A.a[9], Y));
    u64 B2 = f2fma(Q, W, P2);

    return f2fma(T6, A.a[0], f2fma(T3, B3, f2mul(T2, B2)));
}

// Scalar path (tail only).
__device__ __forceinline__ float eval1(const Prep& p, const float* a) {
    float t2 = p.t * p.t, t3 = t2 * p.t, t6 = t3 * t3;
    float g3 = p.fmr * p.rho, q = p.rho * p.rho;
    float c2p = fmaf(p.cp, p.cp, p.nspsq);
    float s2p = 2.0f * p.sp * p.cp;
    float ctst = p.ct * p.st, st2 = p.st * p.st;
    float x1 = fmaf(p.cp, a[3], p.sp * a[4]);
    x1 = fmaf(p.ct, a[2], p.st * x1);
    float b3 = fmaf(p.tmr, a[1], p.r * x1);
    float x2 = fmaf(p.cp, a[7], p.sp * a[8]);
    x2 = fmaf(p.ct, a[6], p.st * x2);
    float p2 = fmaf(p.l30, a[5], g3 * x2);
    float y = fmaf(p.cp, a[10], p.sp * a[11]);
    y *= ctst;
    float z = fmaf(c2p, a[12], s2p * a[13]);
    float w = fmaf(st2, z, fmaf(p.ct2t, a[9], y));
    float b2 = fmaf(q, w, p2);
    return fmaf(t6, a[0], fmaf(t3, b3, t2 * b2));
}

__global__ __launch_bounds__(256)
void orbital_eval_kernel(const float* __restrict__ pos,
                         const float* __restrict__ coeffs,
                         float* __restrict__ out,
                         int n4, int n) {
    int i = blockIdx.x * blockDim.x + threadIdx.x;

    float c[14];
#pragma unroll
    for (int k = 0; k < 14; k++) c[k] = __ldg(&coeffs[k]);

    // Combined coefficients: norm constants folded in.
    float ac[14];
    ac[0]  =  Y00f * 2.0f * c[0];
    ac[1]  =  Y00f * K20f * c[1];
    ac[2]  =  N10f * K21f * c[3];
    ac[3]  = -N10f * K21f * c[4];
    ac[4]  = -N10f * K21f * c[2];
    ac[5]  =  Y00f * K30f * c[5];
    ac[6]  =  N10f * K31f * c[7];
    ac[7]  = -N10f * K31f * c[8];
    ac[8]  = -N10f * K31f * c[6];
    ac[9]  =  N20f * K32f * c[11];
    ac[10] =  C21f * K32f * c[12];
    ac[11] =  C21f * K32f * c[10];
    ac[12] =  C22f * K32f * c[13];
    ac[13] =  C22f * K32f * c[9];

    A14 A;
#pragma unroll
    for (int k = 0; k < 14; k++) A.a[k] = pk(ac[k], ac[k]);

    if (i < n4) {
        const float4* p4 = reinterpret_cast<const float4*>(pos);
        float4 va = p4[3 * i + 0];
        float4 vb = p4[3 * i + 1];
        float4 vc = p4[3 * i + 2];
        // 4 points: (va.x,va.y,va.z) (va.w,vb.x,vb.y) (vb.z,vb.w,vc.x) (vc.y,vc.z,vc.w)
        Prep q0 = prep(va.x, va.y, va.z);
        Prep q1 = prep(va.w, vb.x, vb.y);
        Prep q2 = prep(vb.z, vb.w, vc.x);
        Prep q3 = prep(vc.y, vc.z, vc.w);

        u64 o01 = eval_pair(q0, q1, A);
        u64 o23 = eval_pair(q2, q3, A);

        float4 o;
        upk(o01, o.x, o.y);
        upk(o23, o.z, o.w);
        reinterpret_cast<float4*>(out)[i] = o;
    }

    // Scalar tail (n % 4 != 0)
    int tail = n - n4 * 4;
    if (i < tail) {
        int idx = n4 * 4 + i;
        Prep p = prep(pos[3 * idx], pos[3 * idx + 1], pos[3 * idx + 2]);
        out[idx] = eval1(p, ac);
    }
}

extern "C" void kernel_launch(void* const* d_in, const int* in_sizes, int n_in,
                              void* d_out, int out_size) {
    const float* pos    = (const float*)d_in[0];   // (2048, 4096, 3) fp32
    const float* coeffs = (const float*)d_in[1];   // (14,) fp32
    float* out          = (float*)d_out;           // (2048, 4096) fp32

    int n  = out_size;
    int n4 = n / 4;

    int threads = 256;
    int groups  = (n4 > 0) ? n4 : 1;
    int blocks  = (groups + threads - 1) / threads;
    orbital_eval_kernel<<<blocks, threads>>>(pos, coeffs, out, n4, n);
}

// round 3
// speedup vs baseline: 1.0118x; 1.0094x over previous
#include <cuda_runtime.h>

// Closed-form normalization constants.
#define Y00f  0.28209479177387814f    // 1/(2*sqrt(pi))
#define N10f  0.48860251190291992f    // sqrt(3/(4pi))
#define N20f  0.63078313050504001f    // sqrt(5/(4pi))
#define C21f  (-1.09254843059207907f) // -(1/2)*sqrt(15/pi)
#define C22f  0.54627421529603953f    // (1/4)*sqrt(15/pi)
#define K20f  0.35355339059327379f    // 1/(2*sqrt(2))
#define K21f  0.20412414523193152f    // 1/(2*sqrt(6))
#define K30f  0.06415002990995843f    // 1/(9*sqrt(3))
#define K31f  0.04536092116208279f    // sqrt(1/486)
#define K32f  0.02028602047074832f    // sqrt(8/19440)

typedef unsigned long long u64;

__device__ u64 g_A[14];   // pre-packed combined coefficients (lo==hi)

__device__ __forceinline__ u64 pk(float lo, float hi) {
    u64 r; asm("mov.b64 %0,{%1,%2};" : "=l"(r) : "f"(lo), "f"(hi)); return r;
}
__device__ __forceinline__ void upk(u64 v, float& lo, float& hi) {
    asm("mov.b64 {%0,%1},%2;" : "=f"(lo), "=f"(hi) : "l"(v));
}
__device__ __forceinline__ u64 f2mul(u64 a, u64 b) {
    u64 d; asm("mul.rn.f32x2 %0,%1,%2;" : "=l"(d) : "l"(a), "l"(b)); return d;
}
__device__ __forceinline__ u64 f2fma(u64 a, u64 b, u64 c) {
    u64 d; asm("fma.rn.f32x2 %0,%1,%2,%3;" : "=l"(d) : "l"(a), "l"(b), "l"(c)); return d;
}
__device__ __forceinline__ u64 f2add(u64 a, u64 b) {
    u64 d; asm("add.rn.f32x2 %0,%1,%2;" : "=l"(d) : "l"(a), "l"(b)); return d;
}

// One-warp setup: fold norms into coefficients, pack, store to global table.
__global__ void setup_coeffs_kernel(const float* __restrict__ coeffs) {
    if (threadIdx.x == 0) {
        float c[14];
#pragma unroll
        for (int k = 0; k < 14; k++) c[k] = coeffs[k];
        float ac[14];
        ac[0]  =  Y00f * 2.0f * c[0];
        ac[1]  =  Y00f * K20f * c[1];
        ac[2]  =  N10f * K21f * c[3];
        ac[3]  = -N10f * K21f * c[4];
        ac[4]  = -N10f * K21f * c[2];
        ac[5]  =  Y00f * K30f * c[5];
        ac[6]  =  N10f * K31f * c[7];
        ac[7]  = -N10f * K31f * c[8];
        ac[8]  = -N10f * K31f * c[6];
        ac[9]  =  N20f * K32f * c[11];
        ac[10] =  C21f * K32f * c[12];
        ac[11] =  C21f * K32f * c[10];
        ac[12] =  C22f * K32f * c[13];
        ac[13] =  C22f * K32f * c[9];
#pragma unroll
        for (int k = 0; k < 14; k++) g_A[k] = pk(ac[k], ac[k]);
    }
}

// Per-point scalar prep: MUFU ops + constant-immediate ops only (FFMA-imm rt=1).
struct Prep { float r, t, ct, st, cp, sp, rho, tmr, fmr, l30, nspsq, ct2t; };

__device__ __forceinline__ Prep prep(float r, float th, float ph) {
    Prep p;
    p.r = r;
    __sincosf(th, &p.st, &p.ct);
    __sincosf(ph, &p.sp, &p.cp);
    p.t     = __expf(r * (-1.0f / 6.0f));      // e^{-r/6}
    p.rho   = r * (2.0f / 3.0f);
    p.tmr   = 2.0f - r;
    p.fmr   = 4.0f - p.rho;
    p.l30   = fmaf(p.rho - 6.0f, p.rho, 6.0f); // rho^2 - 6 rho + 6
    p.nspsq = p.sp * (-p.sp);                  // -sin^2(phi)
    p.ct2t  = fmaf(p.ct * p.ct, 1.5f, -0.5f);  // (3cos^2-1)/2
    return p;
}

// Packed evaluation of two points.
__device__ __forceinline__ u64 eval_pair(const Prep& p0, const Prep& p1, const u64* a) {
    u64 R   = pk(p0.r,   p1.r),   T    = pk(p0.t,    p1.t);
    u64 CT  = pk(p0.ct,  p1.ct),  ST   = pk(p0.st,   p1.st);
    u64 CP  = pk(p0.cp,  p1.cp),  SP   = pk(p0.sp,   p1.sp);
    u64 RHO = pk(p0.rho, p1.rho), TMR  = pk(p0.tmr,  p1.tmr);
    u64 FMR = pk(p0.fmr, p1.fmr), L30  = pk(p0.l30,  p1.l30);
    u64 NSQ = pk(p0.nspsq, p1.nspsq), CT2T = pk(p0.ct2t, p1.ct2t);

    u64 T2 = f2mul(T, T), T3 = f2mul(T2, T), T6 = f2mul(T3, T3);
    u64 G3 = f2mul(FMR, RHO);           // (4-rho)*rho
    u64 Q  = f2mul(RHO, RHO);           // rho^2
    u64 C2P  = f2fma(CP, CP, NSQ);      // cos(2phi)
    u64 SPCP = f2mul(SP, CP);
    u64 S2P  = f2add(SPCP, SPCP);       // sin(2phi)
    u64 CTST = f2mul(CT, ST), ST2 = f2mul(ST, ST);

    // n=2 block (×t3)
    u64 X1 = f2fma(CP, a[3], f2mul(SP, a[4]));
    X1     = f2fma(CT, a[2], f2mul(ST, X1));
    u64 B3 = f2fma(TMR, a[1], f2mul(R, X1));

    // n=3, l=0..1 block (×t2)
    u64 X2 = f2fma(CP, a[7], f2mul(SP, a[8]));
    X2     = f2fma(CT, a[6], f2mul(ST, X2));
    u64 P2 = f2fma(L30, a[5], f2mul(G3, X2));

    // n=3, l=2 block
    u64 Y = f2fma(CP, a[10], f2mul(SP, a[11]));
    Y     = f2mul(CTST, Y);
    u64 Z = f2fma(C2P, a[12], f2mul(S2P, a[13]));
    u64 W = f2fma(ST2, Z, f2fma(CT2T, a[9], Y));
    u64 B2 = f2fma(Q, W, P2);

    return f2fma(T6, a[0], f2fma(T3, B3, f2mul(T2, B2)));
}

// Scalar path (tail only).
__device__ __forceinline__ float eval1(const Prep& p, const u64* a) {
    float av[14];
#pragma unroll
    for (int k = 0; k < 14; k++) { float hi; upk(a[k], av[k], hi); }
    float t2 = p.t * p.t, t3 = t2 * p.t, t6 = t3 * t3;
    float g3 = p.fmr * p.rho, q = p.rho * p.rho;
    float c2p = fmaf(p.cp, p.cp, p.nspsq);
    float s2p = 2.0f * p.sp * p.cp;
    float ctst = p.ct * p.st, st2 = p.st * p.st;
    float x1 = fmaf(p.cp, av[3], p.sp * av[4]);
    x1 = fmaf(p.ct, av[2], p.st * x1);
    float b3 = fmaf(p.tmr, av[1], p.r * x1);
    float x2 = fmaf(p.cp, av[7], p.sp * av[8]);
    x2 = fmaf(p.ct, av[6], p.st * x2);
    float p2 = fmaf(p.l30, av[5], g3 * x2);
    float y = fmaf(p.cp, av[10], p.sp * av[11]);
    y *= ctst;
    float z = fmaf(c2p, av[12], s2p * av[13]);
    float w = fmaf(st2, z, fmaf(p.ct2t, av[9], y));
    float b2 = fmaf(q, w, p2);
    return fmaf(t6, av[0], fmaf(t3, b3, t2 * b2));
}

__global__ __launch_bounds__(128)
void orbital_eval_kernel(const float* __restrict__ pos,
                         float* __restrict__ out,
                         int n4, int n) {
    int i = blockIdx.x * blockDim.x + threadIdx.x;

    // Load pre-packed combined coefficients (7x 16B, L1-broadcast).
    u64 a[14];
    {
        const ulonglong2* Ap = reinterpret_cast<const ulonglong2*>(g_A);
#pragma unroll
        for (int k = 0; k < 7; k++) {
            ulonglong2 v = __ldg(&Ap[k]);
            a[2 * k]     = v.x;
            a[2 * k + 1] = v.y;
        }
    }

    if (i < n4) {
        const float4* p4 = reinterpret_cast<const float4*>(pos);
        float4 va = p4[3 * i + 0];
        float4 vb = p4[3 * i + 1];
        float4 vc = p4[3 * i + 2];
        float2* o2 = reinterpret_cast<float2*>(out);

        // Pair 0: points (va.x,va.y,va.z) and (va.w,vb.x,vb.y)
        {
            Prep q0 = prep(va.x, va.y, va.z);
            Prep q1 = prep(va.w, vb.x, vb.y);
            u64 o01 = eval_pair(q0, q1, a);
            float2 o; upk(o01, o.x, o.y);
            o2[2 * i] = o;
        }
        // Pair 1: points (vb.z,vb.w,vc.x) and (vc.y,vc.z,vc.w)
        {
            Prep q2 = prep(vb.z, vb.w, vc.x);
            Prep q3 = prep(vc.y, vc.z, vc.w);
            u64 o23 = eval_pair(q2, q3, a);
            float2 o; upk(o23, o.x, o.y);
            o2[2 * i + 1] = o;
        }
    }

    // Scalar tail (n % 4 != 0)
    int tail = n - n4 * 4;
    if (i < tail) {
        int idx = n4 * 4 + i;
        Prep p = prep(pos[3 * idx], pos[3 * idx + 1], pos[3 * idx + 2]);
        out[idx] = eval1(p, a);
    }
}

extern "C" void kernel_launch(void* const* d_in, const int* in_sizes, int n_in,
                              void* d_out, int out_size) {
    const float* pos    = (const float*)d_in[0];   // (2048, 4096, 3) fp32
    const float* coeffs = (const float*)d_in[1];   // (14,) fp32
    float* out          = (float*)d_out;           // (2048, 4096) fp32

    int n  = out_size;
    int n4 = n / 4;

    setup_coeffs_kernel<<<1, 32>>>(coeffs);

    int threads = 128;
    int groups  = (n4 > 0) ? n4 : 1;
    int blocks  = (groups + threads - 1) / threads;
    orbital_eval_kernel<<<blocks, threads>>>(pos, out, n4, n);
}